// round 4
// baseline (speedup 1.0000x reference)
#include <cuda_runtime.h>
#include <cuda_bf16.h>
#include <math.h>
#include <cstdint>

#define BB 8192
#define DD 1024
#define INV_TEMP (1.0f / 0.07f)

// ---- scratch (device globals; no allocation allowed) ----
__device__ float g_Z[BB];
__device__ float g_Sp[BB];
__device__ float g_norm2[BB];
__device__ float g_dotM[BB];
__device__ float g_M[DD];
__device__ float g_shell_m;
__device__ float g_shell_h;
__device__ int   g_nm;
__device__ int   g_nh;
__device__ __nv_bfloat16 g_Ebf[(size_t)BB * DD];   // bf16 copy of embeddings

// ======================= helpers =======================
__device__ __forceinline__ uint32_t smem_u32(const void* p) {
    return (uint32_t)__cvta_generic_to_shared(p);
}
#define SWZ(o) ((o) ^ (((o) >> 3) & 0x70))

__device__ __forceinline__ void cp_async16(uint32_t dst, const void* src) {
    asm volatile("cp.async.cg.shared.global [%0], [%1], 16;"
                 :: "r"(dst), "l"(src) : "memory");
}
__device__ __forceinline__ void cp_commit() {
    asm volatile("cp.async.commit_group;" ::: "memory");
}
template <int N>
__device__ __forceinline__ void cp_wait() {
    asm volatile("cp.async.wait_group %0;" :: "n"(N) : "memory");
}
__device__ __forceinline__ void ldsm_x4(uint32_t* r, uint32_t addr) {
    asm volatile("ldmatrix.sync.aligned.m8n8.x4.shared.b16 {%0,%1,%2,%3}, [%4];"
                 : "=r"(r[0]), "=r"(r[1]), "=r"(r[2]), "=r"(r[3]) : "r"(addr));
}
__device__ __forceinline__ void mma_bf16(float* d, const uint32_t* a,
                                         uint32_t b0, uint32_t b1) {
    asm volatile(
        "mma.sync.aligned.m16n8k16.row.col.f32.bf16.bf16.f32 "
        "{%0,%1,%2,%3}, {%4,%5,%6,%7}, {%8,%9}, {%0,%1,%2,%3};"
        : "+f"(d[0]), "+f"(d[1]), "+f"(d[2]), "+f"(d[3])
        : "r"(a[0]), "r"(a[1]), "r"(a[2]), "r"(a[3]), "r"(b0), "r"(b1));
}

// ======================= small kernels =======================
__global__ void init_kernel() {
    int t = blockIdx.x * blockDim.x + threadIdx.x;
    if (t < BB) g_Z[t] = 0.0f;
    if (t < DD) g_M[t] = 0.0f;
    if (t == 0) { g_shell_m = 0.0f; g_shell_h = 0.0f; g_nm = 0; g_nh = 0; }
}

// per-row stats + fp32->bf16 conversion
__global__ void row_stats_kernel(const float* __restrict__ E,
                                 const float* __restrict__ c,
                                 const float* __restrict__ rm_p,
                                 const float* __restrict__ rh_p,
                                 const int* __restrict__ labels,
                                 float* __restrict__ out,
                                 int dist_off) {
    const int i = blockIdx.x;
    const int t = threadIdx.x;  // 128
    const float4* e4 = (const float4*)(E + (size_t)i * DD);
    const float4* c4 = (const float4*)c;

    float dc = 0.f, n2 = 0.f, cn2 = 0.f;
    #pragma unroll
    for (int k = t; k < DD / 4; k += 128) {
        float4 e = e4[k];
        float4 cc = c4[k];
        dc  += e.x * cc.x + e.y * cc.y + e.z * cc.z + e.w * cc.w;
        n2  += e.x * e.x + e.y * e.y + e.z * e.z + e.w * e.w;
        cn2 += cc.x * cc.x + cc.y * cc.y + cc.z * cc.z + cc.w * cc.w;
        __nv_bfloat162 lo = __floats2bfloat162_rn(e.x, e.y);
        __nv_bfloat162 hi = __floats2bfloat162_rn(e.z, e.w);
        __nv_bfloat162* dst = (__nv_bfloat162*)(g_Ebf + (size_t)i * DD + k * 4);
        dst[0] = lo; dst[1] = hi;
    }
    __shared__ float s0[128], s1[128], s2[128];
    s0[t] = dc; s1[t] = n2; s2[t] = cn2;
    __syncthreads();
    for (int o = 64; o > 0; o >>= 1) {
        if (t < o) { s0[t] += s0[t + o]; s1[t] += s1[t + o]; s2[t] += s2[t + o]; }
        __syncthreads();
    }
    if (t == 0) {
        float dot = s0[0], nn = s1[0], cn = s2[0];
        float dist = sqrtf(fmaxf(nn - 2.0f * dot + cn, 0.0f));
        out[dist_off + i] = dist;
        g_Sp[i]    = dot * INV_TEMP;
        g_norm2[i] = nn;
        if (labels[i] == 0) {
            atomicAdd(&g_nm, 1);
            float r = fmaxf(dist - rm_p[0], 0.0f);
            atomicAdd(&g_shell_m, r * r);
        } else {
            atomicAdd(&g_nh, 1);
            float r = fmaxf(rh_p[0] - dist, 0.0f);
            atomicAdd(&g_shell_h, r * r);
        }
    }
}

// machine column-sum from bf16 copy
__global__ void msum_kernel(const int* __restrict__ labels) {
    const int col4 = blockIdx.x * blockDim.x + threadIdx.x;  // 0..255 (groups of 4)
    const int r0  = blockIdx.y * (BB / 64);
    float s0 = 0.f, s1 = 0.f, s2 = 0.f, s3 = 0.f;
    #pragma unroll 4
    for (int r = r0; r < r0 + (BB / 64); ++r) {
        if (labels[r] == 0) {
            const __nv_bfloat162* p =
                (const __nv_bfloat162*)(g_Ebf + (size_t)r * DD + col4 * 4);
            float2 a = __bfloat1622float2(p[0]);
            float2 b = __bfloat1622float2(p[1]);
            s0 += a.x; s1 += a.y; s2 += b.x; s3 += b.y;
        }
    }
    atomicAdd(&g_M[col4 * 4 + 0], s0);
    atomicAdd(&g_M[col4 * 4 + 1], s1);
    atomicAdd(&g_M[col4 * 4 + 2], s2);
    atomicAdd(&g_M[col4 * 4 + 3], s3);
}

__global__ void dotM_kernel() {
    const int warp = threadIdx.x >> 5;
    const int lane = threadIdx.x & 31;
    const int i = blockIdx.x * 8 + warp;
    const float4* m4 = (const float4*)g_M;
    float s = 0.0f;
    #pragma unroll
    for (int k = lane; k < DD / 4; k += 32) {
        const __nv_bfloat162* p = (const __nv_bfloat162*)(g_Ebf + (size_t)i * DD + k * 4);
        float2 a = __bfloat1622float2(p[0]);
        float2 b = __bfloat1622float2(p[1]);
        float4 m = m4[k];
        s += a.x * m.x + a.y * m.y + b.x * m.z + b.y * m.w;
    }
    #pragma unroll
    for (int o = 16; o > 0; o >>= 1) s += __shfl_down_sync(0xffffffffu, s, o);
    if (lane == 0) g_dotM[i] = s;
}

// ======================= HMMA GEMM + exp-sum =======================
// CTA tile 256 (rows) x 128 (cols); warp grid 4x2, warp tile 64x64.
// Triangle rule: keep tile iff tj >= 2*ti; col-scatter iff tj >= 2*ti+2;
// diagonal zeroing iff (tj>>1)==ti.
#define BK 64
#define NCHUNK (DD / BK)           // 16
#define NSTG 3
#define A_KB 32768                 // 256 rows x 128 B
#define B_KB 16384                 // 128 rows x 128 B
#define STAGE_BYTES (A_KB + B_KB)  // 48 KB
#define SMEM_TOTAL (NSTG * STAGE_BYTES)

__global__ void __launch_bounds__(256, 1)
gemm_expsum_kernel() {
    const int ti = blockIdx.y;            // 0..31 (256-row blocks)
    const int tj = blockIdx.x;            // 0..63 (128-col blocks)
    if (tj < 2 * ti) return;
    const bool straddle = ((tj >> 1) == ti);
    const bool scatter  = (tj >= 2 * ti + 2);
    const int ib = ti * 256;
    const int jb = tj * 128;

    extern __shared__ char smem[];
    const uint32_t sbase = smem_u32(smem);
    const int tid  = threadIdx.x;
    const int lane = tid & 31;
    const int wid  = tid >> 5;
    const int wm   = wid >> 1;            // 0..3 row group (64 rows)
    const int wn   = wid & 1;             // 0..1 col group (64 cols)

    const int lrow = tid >> 3;            // 0..31
    const int lch  = tid & 7;             // 16B chunk in 128B row

    // prologue: stages 0,1
    #pragma unroll
    for (int s = 0; s < NSTG - 1; ++s) {
        const uint32_t aB = sbase + s * STAGE_BYTES;
        const uint32_t bB = aB + A_KB;
        const size_t kk = (size_t)s * BK;
        #pragma unroll
        for (int r = 0; r < 8; ++r) {
            const int row = lrow + r * 32;
            cp_async16(aB + SWZ(row * 128 + lch * 16),
                       g_Ebf + (size_t)(ib + row) * DD + kk + lch * 8);
        }
        #pragma unroll
        for (int r = 0; r < 4; ++r) {
            const int row = lrow + r * 32;
            cp_async16(bB + SWZ(row * 128 + lch * 16),
                       g_Ebf + (size_t)(jb + row) * DD + kk + lch * 8);
        }
        cp_commit();
    }

    float acc[4][8][4];
    #pragma unroll
    for (int mt = 0; mt < 4; ++mt)
        #pragma unroll
        for (int nt = 0; nt < 8; ++nt)
            #pragma unroll
            for (int q = 0; q < 4; ++q) acc[mt][nt][q] = 0.0f;

    for (int c = 0; c < NCHUNK; ++c) {
        cp_wait<1>();
        __syncthreads();

        if (c + NSTG - 1 < NCHUNK) {
            const int s = (c + NSTG - 1) % NSTG;
            const uint32_t aB = sbase + s * STAGE_BYTES;
            const uint32_t bB = aB + A_KB;
            const size_t kk = (size_t)(c + NSTG - 1) * BK;
            #pragma unroll
            for (int r = 0; r < 8; ++r) {
                const int row = lrow + r * 32;
                cp_async16(aB + SWZ(row * 128 + lch * 16),
                           g_Ebf + (size_t)(ib + row) * DD + kk + lch * 8);
            }
            #pragma unroll
            for (int r = 0; r < 4; ++r) {
                const int row = lrow + r * 32;
                cp_async16(bB + SWZ(row * 128 + lch * 16),
                           g_Ebf + (size_t)(jb + row) * DD + kk + lch * 8);
            }
        }
        cp_commit();

        const uint32_t aB = sbase + (c % NSTG) * STAGE_BYTES;
        const uint32_t bB = aB + A_KB;
        #pragma unroll
        for (int kq = 0; kq < 4; ++kq) {   // 4 x k16
            uint32_t b[4][4];
            #pragma unroll
            for (int nq = 0; nq < 4; ++nq) {
                const int row = wn * 64 + nq * 16 + (lane & 7) + ((lane >> 4) << 3);
                const int byc = kq * 32 + ((lane >> 3) & 1) * 16;
                ldsm_x4(b[nq], bB + SWZ(row * 128 + byc));
            }
            #pragma unroll
            for (int mt = 0; mt < 4; ++mt) {
                uint32_t a[4];
                const int row = wm * 64 + mt * 16 + (lane & 15);
                const int byc = kq * 32 + (lane >> 4) * 16;
                ldsm_x4(a, aB + SWZ(row * 128 + byc));
                #pragma unroll
                for (int nt = 0; nt < 8; ++nt)
                    mma_bf16(acc[mt][nt], a,
                             b[nt >> 1][(nt & 1) * 2], b[nt >> 1][(nt & 1) * 2 + 1]);
            }
        }
        __syncthreads();
    }

    // ---------------- epilogue: exp + row/col sums ----------------
    float rowp[4][2];
    float colp[8][2];
    #pragma unroll
    for (int mt = 0; mt < 4; ++mt) { rowp[mt][0] = 0.f; rowp[mt][1] = 0.f; }
    #pragma unroll
    for (int nt = 0; nt < 8; ++nt) { colp[nt][0] = 0.f; colp[nt][1] = 0.f; }

    const int r_lo = (lane >> 2);
    const int c_lo = (lane & 3) * 2;

    #pragma unroll
    for (int mt = 0; mt < 4; ++mt) {
        const int gi0 = ib + wm * 64 + mt * 16 + r_lo;
        const int gi1 = gi0 + 8;
        #pragma unroll
        for (int nt = 0; nt < 8; ++nt) {
            const int gj0 = jb + wn * 64 + nt * 8 + c_lo;
            const int gj1 = gj0 + 1;
            float e00 = __expf(acc[mt][nt][0] * INV_TEMP);
            float e01 = __expf(acc[mt][nt][1] * INV_TEMP);
            float e10 = __expf(acc[mt][nt][2] * INV_TEMP);
            float e11 = __expf(acc[mt][nt][3] * INV_TEMP);
            if (straddle) {
                if (gi0 == gj0) e00 = 0.0f;
                if (gi0 == gj1) e01 = 0.0f;
                if (gi1 == gj0) e10 = 0.0f;
                if (gi1 == gj1) e11 = 0.0f;
            }
            rowp[mt][0] += e00 + e01;
            rowp[mt][1] += e10 + e11;
            colp[nt][0] += e00 + e10;
            colp[nt][1] += e01 + e11;
        }
    }

    #pragma unroll
    for (int mt = 0; mt < 4; ++mt)
        #pragma unroll
        for (int h = 0; h < 2; ++h) {
            float v = rowp[mt][h];
            v += __shfl_xor_sync(0xffffffffu, v, 1);
            v += __shfl_xor_sync(0xffffffffu, v, 2);
            rowp[mt][h] = v;
        }
    #pragma unroll
    for (int nt = 0; nt < 8; ++nt)
        #pragma unroll
        for (int j = 0; j < 2; ++j) {
            float v = colp[nt][j];
            v += __shfl_xor_sync(0xffffffffu, v, 4);
            v += __shfl_xor_sync(0xffffffffu, v, 8);
            v += __shfl_xor_sync(0xffffffffu, v, 16);
            colp[nt][j] = v;
        }

    // reuse (now dead) stage memory for cross-warp reductions
    float* rowred = (float*)smem;              // [256][2]
    float* colred = (float*)(smem + 2048);     // [128][4]
    __syncthreads();

    if ((lane & 3) == 0) {
        #pragma unroll
        for (int mt = 0; mt < 4; ++mt)
            #pragma unroll
            for (int h = 0; h < 2; ++h) {
                const int row = wm * 64 + mt * 16 + r_lo + 8 * h;
                rowred[row * 2 + wn] = rowp[mt][h];
            }
    }
    if (lane < 4) {
        #pragma unroll
        for (int nt = 0; nt < 8; ++nt)
            #pragma unroll
            for (int j = 0; j < 2; ++j) {
                const int col = wn * 64 + nt * 8 + lane * 2 + j;
                colred[col * 4 + wm] = colp[nt][j];
            }
    }
    __syncthreads();

    atomicAdd(&g_Z[ib + tid], rowred[tid * 2] + rowred[tid * 2 + 1]);
    if (scatter && tid < 128) {
        float cs = colred[tid * 4] + colred[tid * 4 + 1] +
                   colred[tid * 4 + 2] + colred[tid * 4 + 3];
        atomicAdd(&g_Z[jb + tid], cs);
    }
}

// ======================= finalize =======================
__global__ void finalize_kernel(const int* __restrict__ labels,
                                float* __restrict__ out) {
    const int t = threadIdx.x;  // 256
    __shared__ float sh[256];

    const int nm_i = g_nm;
    const int nh_i = g_nh;
    const float nm_den = fmaxf((float)nm_i, 1.0f);
    const float nh_den = fmaxf((float)nh_i, 1.0f);

    float mx = -1e30f;
    for (int i = t; i < BB; i += 256) mx = fmaxf(mx, g_Sp[i]);
    sh[t] = mx; __syncthreads();
    for (int o = 128; o > 0; o >>= 1) { if (t < o) sh[t] = fmaxf(sh[t], sh[t + o]); __syncthreads(); }
    const float smax = sh[0];
    __syncthreads();

    float sumexp_p = 0.0f, sum_m_sp = 0.0f, con_sum = 0.0f;
    for (int i = t; i < BB; i += 256) {
        float sp = g_Sp[i];
        sumexp_p += __expf(sp - smax);
        bool m = (labels[i] == 0);
        float lse = logf(g_Z[i] + __expf(sp));
        float pos = g_dotM[i] * INV_TEMP - (m ? g_norm2[i] * INV_TEMP : 0.0f) + sp;
        float al = lse - pos / nm_den;
        if (m) { sum_m_sp += sp; con_sum += al; }
    }
    sh[t] = sumexp_p; __syncthreads();
    for (int o = 128; o > 0; o >>= 1) { if (t < o) sh[t] += sh[t + o]; __syncthreads(); }
    sumexp_p = sh[0]; __syncthreads();
    sh[t] = sum_m_sp; __syncthreads();
    for (int o = 128; o > 0; o >>= 1) { if (t < o) sh[t] += sh[t + o]; __syncthreads(); }
    sum_m_sp = sh[0]; __syncthreads();
    sh[t] = con_sum; __syncthreads();
    for (int o = 128; o > 0; o >>= 1) { if (t < o) sh[t] += sh[t + o]; __syncthreads(); }
    con_sum = sh[0];

    if (t == 0) {
        float lse_p = smax + logf(sumexp_p);
        float proto_loss = lse_p - sum_m_sp / nm_den;
        float loss_con = (con_sum + proto_loss) / fmaxf((float)(nm_i + 1), 1.0f);
        if (!(nm_i > 0 && nh_i > 0)) loss_con = 0.0f;
        float loss_m = g_shell_m / nm_den;
        float loss_h = g_shell_h / nh_den;
        float loss_shell = loss_m + loss_h;
        out[0] = loss_shell + loss_con;
        out[1] = loss_shell;
        out[2] = loss_m;
        out[3] = loss_h;
        out[4] = loss_con;
    }
}

extern "C" void kernel_launch(void* const* d_in, const int* in_sizes, int n_in,
                              void* d_out, int out_size) {
    const float* E      = (const float*)d_in[0];
    const float* center = (const float*)d_in[1];
    const float* rm     = (const float*)d_in[2];
    const float* rh     = (const float*)d_in[3];
    const int*   labels = (const int*)d_in[4];
    float* out = (float*)d_out;

    const int dist_off = out_size - BB;

    cudaFuncSetAttribute(gemm_expsum_kernel,
                         cudaFuncAttributeMaxDynamicSharedMemorySize, SMEM_TOTAL);

    init_kernel<<<(BB + 255) / 256, 256>>>();
    row_stats_kernel<<<BB, 128>>>(E, center, rm, rh, labels, out, dist_off);
    msum_kernel<<<dim3(DD / 4 / 256, 64), 256>>>(labels);
    dotM_kernel<<<BB / 8, 256>>>();
    gemm_expsum_kernel<<<dim3(64, 32), 256, SMEM_TOTAL>>>();
    finalize_kernel<<<1, 256>>>(labels, out);
}

// round 5
// speedup vs baseline: 1.1054x; 1.1054x over previous
#include <cuda_runtime.h>
#include <cuda_bf16.h>
#include <math.h>
#include <cstdint>

#define BB 8192
#define DD 1024
#define INV_TEMP (1.0f / 0.07f)

// ---- scratch (device globals; no allocation allowed) ----
__device__ float g_Z[BB];
__device__ float g_Sp[BB];
__device__ float g_norm2[BB];
__device__ float g_dotM[BB];
__device__ float g_M[DD];
__device__ float g_shell_m;
__device__ float g_shell_h;
__device__ int   g_nm;
__device__ int   g_nh;
__device__ __nv_bfloat16 g_Ebf[(size_t)BB * DD];   // bf16 copy of embeddings

// ======================= helpers =======================
__device__ __forceinline__ uint32_t smem_u32(const void* p) {
    return (uint32_t)__cvta_generic_to_shared(p);
}
#define SWZ(o) ((o) ^ (((o) >> 3) & 0x70))

__device__ __forceinline__ void cp_async16(uint32_t dst, const void* src) {
    asm volatile("cp.async.cg.shared.global [%0], [%1], 16;"
                 :: "r"(dst), "l"(src) : "memory");
}
__device__ __forceinline__ void cp_commit() {
    asm volatile("cp.async.commit_group;" ::: "memory");
}
template <int N>
__device__ __forceinline__ void cp_wait() {
    asm volatile("cp.async.wait_group %0;" :: "n"(N) : "memory");
}
__device__ __forceinline__ void ldsm_x4(uint32_t* r, uint32_t addr) {
    asm volatile("ldmatrix.sync.aligned.m8n8.x4.shared.b16 {%0,%1,%2,%3}, [%4];"
                 : "=r"(r[0]), "=r"(r[1]), "=r"(r[2]), "=r"(r[3]) : "r"(addr));
}
__device__ __forceinline__ void mma_bf16(float* d, const uint32_t* a,
                                         uint32_t b0, uint32_t b1) {
    asm volatile(
        "mma.sync.aligned.m16n8k16.row.col.f32.bf16.bf16.f32 "
        "{%0,%1,%2,%3}, {%4,%5,%6,%7}, {%8,%9}, {%0,%1,%2,%3};"
        : "+f"(d[0]), "+f"(d[1]), "+f"(d[2]), "+f"(d[3])
        : "r"(a[0]), "r"(a[1]), "r"(a[2]), "r"(a[3]), "r"(b0), "r"(b1));
}

// ======================= small kernels =======================
__global__ void init_kernel() {
    int t = blockIdx.x * blockDim.x + threadIdx.x;
    if (t < BB) g_Z[t] = 0.0f;
    if (t < DD) g_M[t] = 0.0f;
    if (t == 0) { g_shell_m = 0.0f; g_shell_h = 0.0f; g_nm = 0; g_nh = 0; }
}

// per-row stats + fp32->bf16 conversion
__global__ void row_stats_kernel(const float* __restrict__ E,
                                 const float* __restrict__ c,
                                 const float* __restrict__ rm_p,
                                 const float* __restrict__ rh_p,
                                 const int* __restrict__ labels,
                                 float* __restrict__ out,
                                 int dist_off) {
    const int i = blockIdx.x;
    const int t = threadIdx.x;  // 128
    const float4* e4 = (const float4*)(E + (size_t)i * DD);
    const float4* c4 = (const float4*)c;

    float dc = 0.f, n2 = 0.f, cn2 = 0.f;
    #pragma unroll
    for (int k = t; k < DD / 4; k += 128) {
        float4 e = e4[k];
        float4 cc = c4[k];
        dc  += e.x * cc.x + e.y * cc.y + e.z * cc.z + e.w * cc.w;
        n2  += e.x * e.x + e.y * e.y + e.z * e.z + e.w * e.w;
        cn2 += cc.x * cc.x + cc.y * cc.y + cc.z * cc.z + cc.w * cc.w;
        __nv_bfloat162 lo = __floats2bfloat162_rn(e.x, e.y);
        __nv_bfloat162 hi = __floats2bfloat162_rn(e.z, e.w);
        __nv_bfloat162* dst = (__nv_bfloat162*)(g_Ebf + (size_t)i * DD + k * 4);
        dst[0] = lo; dst[1] = hi;
    }
    __shared__ float s0[128], s1[128], s2[128];
    s0[t] = dc; s1[t] = n2; s2[t] = cn2;
    __syncthreads();
    for (int o = 64; o > 0; o >>= 1) {
        if (t < o) { s0[t] += s0[t + o]; s1[t] += s1[t + o]; s2[t] += s2[t + o]; }
        __syncthreads();
    }
    if (t == 0) {
        float dot = s0[0], nn = s1[0], cn = s2[0];
        float dist = sqrtf(fmaxf(nn - 2.0f * dot + cn, 0.0f));
        out[dist_off + i] = dist;
        g_Sp[i]    = dot * INV_TEMP;
        g_norm2[i] = nn;
        if (labels[i] == 0) {
            atomicAdd(&g_nm, 1);
            float r = fmaxf(dist - rm_p[0], 0.0f);
            atomicAdd(&g_shell_m, r * r);
        } else {
            atomicAdd(&g_nh, 1);
            float r = fmaxf(rh_p[0] - dist, 0.0f);
            atomicAdd(&g_shell_h, r * r);
        }
    }
}

// machine column-sum from bf16 copy
__global__ void msum_kernel(const int* __restrict__ labels) {
    const int col4 = blockIdx.x * blockDim.x + threadIdx.x;  // groups of 4 cols
    const int r0  = blockIdx.y * (BB / 64);
    float s0 = 0.f, s1 = 0.f, s2 = 0.f, s3 = 0.f;
    #pragma unroll 4
    for (int r = r0; r < r0 + (BB / 64); ++r) {
        if (labels[r] == 0) {
            const __nv_bfloat162* p =
                (const __nv_bfloat162*)(g_Ebf + (size_t)r * DD + col4 * 4);
            float2 a = __bfloat1622float2(p[0]);
            float2 b = __bfloat1622float2(p[1]);
            s0 += a.x; s1 += a.y; s2 += b.x; s3 += b.y;
        }
    }
    atomicAdd(&g_M[col4 * 4 + 0], s0);
    atomicAdd(&g_M[col4 * 4 + 1], s1);
    atomicAdd(&g_M[col4 * 4 + 2], s2);
    atomicAdd(&g_M[col4 * 4 + 3], s3);
}

__global__ void dotM_kernel() {
    const int warp = threadIdx.x >> 5;
    const int lane = threadIdx.x & 31;
    const int i = blockIdx.x * 8 + warp;
    const float4* m4 = (const float4*)g_M;
    float s = 0.0f;
    #pragma unroll
    for (int k = lane; k < DD / 4; k += 32) {
        const __nv_bfloat162* p = (const __nv_bfloat162*)(g_Ebf + (size_t)i * DD + k * 4);
        float2 a = __bfloat1622float2(p[0]);
        float2 b = __bfloat1622float2(p[1]);
        float4 m = m4[k];
        s += a.x * m.x + a.y * m.y + b.x * m.z + b.y * m.w;
    }
    #pragma unroll
    for (int o = 16; o > 0; o >>= 1) s += __shfl_down_sync(0xffffffffu, s, o);
    if (lane == 0) g_dotM[i] = s;
}

// ======================= HMMA GEMM + exp-sum =======================
// CTA tile 128x128, 128 threads (4 warps, 2x2 warp grid, 64x64 warp tile).
// Upper-triangle tiles only (2080 blocks, linearized); off-diagonal tiles
// scatter both row and column exp-sums.
#define BK 64
#define NCHUNK (DD / BK)           // 16
#define NSTG 3
#define TILE_KB 16384              // 128 rows x 128 B
#define STAGE_BYTES (2 * TILE_KB)  // A + B = 32 KB
#define SMEM_TOTAL (NSTG * STAGE_BYTES)
#define NTILE 64                   // 8192/128

__global__ void __launch_bounds__(128, 2)
gemm_expsum_kernel() {
    // linear upper-triangle decode: idx -> (ti, tj), tj >= ti
    const int idx = blockIdx.x;
    int ti = (int)(63.9999f - sqrtf(fmaxf(4095.9f - 2.0f * idx + 0.25f, 0.0f)));
    // fix rounding: f(ti) = ti*64 - ti*(ti-1)/2 must satisfy f(ti) <= idx < f(ti+1)
    while (ti > 0 && idx < ti * NTILE - (ti * (ti - 1)) / 2) --ti;
    while (idx >= (ti + 1) * NTILE - ((ti + 1) * ti) / 2) ++ti;
    const int tj = ti + (idx - (ti * NTILE - (ti * (ti - 1)) / 2));
    const bool isdiag = (ti == tj);
    const int ib = ti * 128;
    const int jb = tj * 128;

    extern __shared__ char smem[];
    const uint32_t sbase = smem_u32(smem);
    const int tid  = threadIdx.x;   // 128
    const int lane = tid & 31;
    const int wid  = tid >> 5;      // 0..3
    const int wm   = wid >> 1;      // 0..1 row group (64 rows)
    const int wn   = wid & 1;       // 0..1 col group (64 cols)

    const int lrow = tid >> 3;      // 0..15
    const int lch  = tid & 7;       // 16B chunk in 128B row

    // prologue: stages 0,1
    #pragma unroll
    for (int s = 0; s < NSTG - 1; ++s) {
        const uint32_t aB = sbase + s * STAGE_BYTES;
        const uint32_t bB = aB + TILE_KB;
        const size_t kk = (size_t)s * BK;
        #pragma unroll
        for (int r = 0; r < 8; ++r) {
            const int row = lrow + r * 16;
            const uint32_t off = SWZ(row * 128 + lch * 16);
            cp_async16(aB + off, g_Ebf + (size_t)(ib + row) * DD + kk + lch * 8);
            cp_async16(bB + off, g_Ebf + (size_t)(jb + row) * DD + kk + lch * 8);
        }
        cp_commit();
    }

    float acc[4][8][4];
    #pragma unroll
    for (int mt = 0; mt < 4; ++mt)
        #pragma unroll
        for (int nt = 0; nt < 8; ++nt)
            #pragma unroll
            for (int q = 0; q < 4; ++q) acc[mt][nt][q] = 0.0f;

    for (int c = 0; c < NCHUNK; ++c) {
        cp_wait<1>();
        __syncthreads();

        if (c + NSTG - 1 < NCHUNK) {
            const int s = (c + NSTG - 1) % NSTG;
            const uint32_t aB = sbase + s * STAGE_BYTES;
            const uint32_t bB = aB + TILE_KB;
            const size_t kk = (size_t)(c + NSTG - 1) * BK;
            #pragma unroll
            for (int r = 0; r < 8; ++r) {
                const int row = lrow + r * 16;
                const uint32_t off = SWZ(row * 128 + lch * 16);
                cp_async16(aB + off, g_Ebf + (size_t)(ib + row) * DD + kk + lch * 8);
                cp_async16(bB + off, g_Ebf + (size_t)(jb + row) * DD + kk + lch * 8);
            }
        }
        cp_commit();

        const uint32_t aB = sbase + (c % NSTG) * STAGE_BYTES;
        const uint32_t bB = aB + TILE_KB;
        #pragma unroll
        for (int kq = 0; kq < 4; ++kq) {   // 4 x k16
            uint32_t b[4][4];
            #pragma unroll
            for (int nq = 0; nq < 4; ++nq) {
                const int row = wn * 64 + nq * 16 + (lane & 7) + ((lane >> 4) << 3);
                const int byc = kq * 32 + ((lane >> 3) & 1) * 16;
                ldsm_x4(b[nq], bB + SWZ(row * 128 + byc));
            }
            #pragma unroll
            for (int mt = 0; mt < 4; ++mt) {
                uint32_t a[4];
                const int row = wm * 64 + mt * 16 + (lane & 15);
                const int byc = kq * 32 + (lane >> 4) * 16;
                ldsm_x4(a, aB + SWZ(row * 128 + byc));
                #pragma unroll
                for (int nt = 0; nt < 8; ++nt)
                    mma_bf16(acc[mt][nt], a,
                             b[nt >> 1][(nt & 1) * 2], b[nt >> 1][(nt & 1) * 2 + 1]);
            }
        }
        __syncthreads();
    }

    // ---------------- epilogue: exp + row/col sums ----------------
    float rowp[4][2];
    float colp[8][2];
    #pragma unroll
    for (int mt = 0; mt < 4; ++mt) { rowp[mt][0] = 0.f; rowp[mt][1] = 0.f; }
    #pragma unroll
    for (int nt = 0; nt < 8; ++nt) { colp[nt][0] = 0.f; colp[nt][1] = 0.f; }

    const int r_lo = (lane >> 2);
    const int c_lo = (lane & 3) * 2;

    #pragma unroll
    for (int mt = 0; mt < 4; ++mt) {
        const int gi0 = ib + wm * 64 + mt * 16 + r_lo;
        const int gi1 = gi0 + 8;
        #pragma unroll
        for (int nt = 0; nt < 8; ++nt) {
            const int gj0 = jb + wn * 64 + nt * 8 + c_lo;
            const int gj1 = gj0 + 1;
            float e00 = __expf(acc[mt][nt][0] * INV_TEMP);
            float e01 = __expf(acc[mt][nt][1] * INV_TEMP);
            float e10 = __expf(acc[mt][nt][2] * INV_TEMP);
            float e11 = __expf(acc[mt][nt][3] * INV_TEMP);
            if (isdiag) {
                if (gi0 == gj0) e00 = 0.0f;
                if (gi0 == gj1) e01 = 0.0f;
                if (gi1 == gj0) e10 = 0.0f;
                if (gi1 == gj1) e11 = 0.0f;
            }
            rowp[mt][0] += e00 + e01;
            rowp[mt][1] += e10 + e11;
            colp[nt][0] += e00 + e10;
            colp[nt][1] += e01 + e11;
        }
    }

    #pragma unroll
    for (int mt = 0; mt < 4; ++mt)
        #pragma unroll
        for (int h = 0; h < 2; ++h) {
            float v = rowp[mt][h];
            v += __shfl_xor_sync(0xffffffffu, v, 1);
            v += __shfl_xor_sync(0xffffffffu, v, 2);
            rowp[mt][h] = v;
        }
    #pragma unroll
    for (int nt = 0; nt < 8; ++nt)
        #pragma unroll
        for (int j = 0; j < 2; ++j) {
            float v = colp[nt][j];
            v += __shfl_xor_sync(0xffffffffu, v, 4);
            v += __shfl_xor_sync(0xffffffffu, v, 8);
            v += __shfl_xor_sync(0xffffffffu, v, 16);
            colp[nt][j] = v;
        }

    // reuse dead stage memory for cross-warp reductions
    float* rowred = (float*)smem;              // [128][2]
    float* colred = (float*)(smem + 1024);     // [128][2]
    __syncthreads();

    if ((lane & 3) == 0) {
        #pragma unroll
        for (int mt = 0; mt < 4; ++mt)
            #pragma unroll
            for (int h = 0; h < 2; ++h) {
                const int row = wm * 64 + mt * 16 + r_lo + 8 * h;
                rowred[row * 2 + wn] = rowp[mt][h];
            }
    }
    if (lane < 4) {
        #pragma unroll
        for (int nt = 0; nt < 8; ++nt)
            #pragma unroll
            for (int j = 0; j < 2; ++j) {
                const int col = wn * 64 + nt * 8 + lane * 2 + j;
                colred[col * 2 + wm] = colp[nt][j];
            }
    }
    __syncthreads();

    atomicAdd(&g_Z[ib + tid], rowred[tid * 2] + rowred[tid * 2 + 1]);
    if (!isdiag) {
        atomicAdd(&g_Z[jb + tid], colred[tid * 2] + colred[tid * 2 + 1]);
    }
}

// ======================= finalize =======================
__global__ void finalize_kernel(const int* __restrict__ labels,
                                float* __restrict__ out) {
    const int t = threadIdx.x;  // 256
    __shared__ float sh[256];

    const int nm_i = g_nm;
    const int nh_i = g_nh;
    const float nm_den = fmaxf((float)nm_i, 1.0f);
    const float nh_den = fmaxf((float)nh_i, 1.0f);

    float mx = -1e30f;
    for (int i = t; i < BB; i += 256) mx = fmaxf(mx, g_Sp[i]);
    sh[t] = mx; __syncthreads();
    for (int o = 128; o > 0; o >>= 1) { if (t < o) sh[t] = fmaxf(sh[t], sh[t + o]); __syncthreads(); }
    const float smax = sh[0];
    __syncthreads();

    float sumexp_p = 0.0f, sum_m_sp = 0.0f, con_sum = 0.0f;
    for (int i = t; i < BB; i += 256) {
        float sp = g_Sp[i];
        sumexp_p += __expf(sp - smax);
        bool m = (labels[i] == 0);
        float lse = logf(g_Z[i] + __expf(sp));
        float pos = g_dotM[i] * INV_TEMP - (m ? g_norm2[i] * INV_TEMP : 0.0f) + sp;
        float al = lse - pos / nm_den;
        if (m) { sum_m_sp += sp; con_sum += al; }
    }
    sh[t] = sumexp_p; __syncthreads();
    for (int o = 128; o > 0; o >>= 1) { if (t < o) sh[t] += sh[t + o]; __syncthreads(); }
    sumexp_p = sh[0]; __syncthreads();
    sh[t] = sum_m_sp; __syncthreads();
    for (int o = 128; o > 0; o >>= 1) { if (t < o) sh[t] += sh[t + o]; __syncthreads(); }
    sum_m_sp = sh[0]; __syncthreads();
    sh[t] = con_sum; __syncthreads();
    for (int o = 128; o > 0; o >>= 1) { if (t < o) sh[t] += sh[t + o]; __syncthreads(); }
    con_sum = sh[0];

    if (t == 0) {
        float lse_p = smax + logf(sumexp_p);
        float proto_loss = lse_p - sum_m_sp / nm_den;
        float loss_con = (con_sum + proto_loss) / fmaxf((float)(nm_i + 1), 1.0f);
        if (!(nm_i > 0 && nh_i > 0)) loss_con = 0.0f;
        float loss_m = g_shell_m / nm_den;
        float loss_h = g_shell_h / nh_den;
        float loss_shell = loss_m + loss_h;
        out[0] = loss_shell + loss_con;
        out[1] = loss_shell;
        out[2] = loss_m;
        out[3] = loss_h;
        out[4] = loss_con;
    }
}

extern "C" void kernel_launch(void* const* d_in, const int* in_sizes, int n_in,
                              void* d_out, int out_size) {
    const float* E      = (const float*)d_in[0];
    const float* center = (const float*)d_in[1];
    const float* rm     = (const float*)d_in[2];
    const float* rh     = (const float*)d_in[3];
    const int*   labels = (const int*)d_in[4];
    float* out = (float*)d_out;

    const int dist_off = out_size - BB;

    cudaFuncSetAttribute(gemm_expsum_kernel,
                         cudaFuncAttributeMaxDynamicSharedMemorySize, SMEM_TOTAL);

    init_kernel<<<(BB + 255) / 256, 256>>>();
    row_stats_kernel<<<BB, 128>>>(E, center, rm, rh, labels, out, dist_off);
    msum_kernel<<<dim3(DD / 4 / 256, 64), 256>>>(labels);
    dotM_kernel<<<BB / 8, 256>>>();
    gemm_expsum_kernel<<<(NTILE * (NTILE + 1)) / 2, 128, SMEM_TOTAL>>>();
    finalize_kernel<<<1, 256>>>(labels, out);
}